// round 5
// baseline (speedup 1.0000x reference)
#include <cuda_runtime.h>
#include <cuda_fp16.h>

#define N_NODES 100000
#define DIM 64
#define N_EDGES 1250000
#define CAP 64          // bucket slots per node; Poisson(12.5) max degree ~40
#define HPR 32          // half2 per row (64 halves)

// Static scratch (no runtime allocation).
__device__ int g_cnt[N_NODES];                    // incoming-edge count per node
__device__ int g_bucket[(size_t)N_NODES * CAP];   // src ids, bucketed by dst
__device__ int g_novf;                            // overflow edge count (normally 0)
__device__ int g_ovf_src[N_EDGES];                // overflow edges (correctness path)
__device__ int g_ovf_dst[N_EDGES];
__device__ __half2 g_xh[(size_t)N_NODES * HPR];   // x in fp16 (128B per row)

// Convert x -> half2 rows; fuse zeroing of counters.
__global__ void convert_zero_kernel(const float* __restrict__ x) {
    int i = blockIdx.x * blockDim.x + threadIdx.x;   // one half2 (2 dims) per thread
    if (i < N_NODES * HPR) {
        float2 v = reinterpret_cast<const float2*>(x)[i];
        g_xh[i] = __float22half2_rn(v);
    }
    if (i < N_NODES) g_cnt[i] = 0;
    if (i == 0) g_novf = 0;
}

// Thread per edge: claim a slot in dst's bucket, store src.
__global__ void fill_kernel(const int* __restrict__ edge_index) {
    int e = blockIdx.x * blockDim.x + threadIdx.x;
    if (e >= N_EDGES) return;
    int src = edge_index[e];
    int dst = edge_index[N_EDGES + e];
    int slot = atomicAdd(&g_cnt[dst], 1);
    if (slot < CAP) {
        g_bucket[(size_t)dst * CAP + slot] = src;
    } else {
        int k = atomicAdd(&g_novf, 1);
        if (k < N_EDGES) { g_ovf_src[k] = src; g_ovf_dst[k] = dst; }
    }
}

// Warp per node: gather fp16 rows, accumulate fp32, mean + normalize + relu.
__global__ void pull_kernel(float* __restrict__ out) {
    int gtid = blockIdx.x * blockDim.x + threadIdx.x;
    int node = gtid >> 5;
    int lane = gtid & 31;
    if (node >= N_NODES) return;

    const unsigned FULL = 0xFFFFFFFFu;
    int cnt = g_cnt[node];
    int m = cnt < CAP ? cnt : CAP;

    float accx = 0.f, accy = 0.f;
    size_t base = (size_t)node * CAP;

    for (int i = 0; i < m; i += 32) {
        int s = 0;
        if (i + lane < m) s = g_bucket[base + i + lane];
        int n = (m - i) < 32 ? (m - i) : 32;

        int j = 0;
        // 4-way unroll: 4 independent L2 gathers in flight per step.
        for (; j + 4 <= n; j += 4) {
            int s0 = __shfl_sync(FULL, s, j + 0);
            int s1 = __shfl_sync(FULL, s, j + 1);
            int s2 = __shfl_sync(FULL, s, j + 2);
            int s3 = __shfl_sync(FULL, s, j + 3);
            __half2 h0 = g_xh[(size_t)s0 * HPR + lane];
            __half2 h1 = g_xh[(size_t)s1 * HPR + lane];
            __half2 h2 = g_xh[(size_t)s2 * HPR + lane];
            __half2 h3 = g_xh[(size_t)s3 * HPR + lane];
            float2 v0 = __half22float2(h0);
            float2 v1 = __half22float2(h1);
            float2 v2 = __half22float2(h2);
            float2 v3 = __half22float2(h3);
            accx += v0.x + v1.x + v2.x + v3.x;
            accy += v0.y + v1.y + v2.y + v3.y;
        }
        for (; j < n; j++) {
            int sj = __shfl_sync(FULL, s, j);
            float2 v = __half22float2(g_xh[(size_t)sj * HPR + lane]);
            accx += v.x;
            accy += v.y;
        }
    }

    // Overflow correctness path (normally dead: g_novf == 0).
    if (cnt > CAP) {
        int no = g_novf;
        if (no > N_EDGES) no = N_EDGES;
        for (int i = 0; i < no; i += 32) {
            int d = -1, s = 0;
            if (i + lane < no) { d = g_ovf_dst[i + lane]; s = g_ovf_src[i + lane]; }
            unsigned mask = __ballot_sync(FULL, d == node);
            while (mask) {
                int j = __ffs(mask) - 1;
                mask &= mask - 1;
                int sj = __shfl_sync(FULL, s, j);
                float2 v = __half22float2(g_xh[(size_t)sj * HPR + lane]);
                accx += v.x;
                accy += v.y;
            }
        }
    }

    float inv_cnt = 1.0f / fmaxf((float)cnt, 1.0f);
    accx *= inv_cnt;
    accy *= inv_cnt;

    float ss = accx * accx + accy * accy;
    #pragma unroll
    for (int off = 16; off > 0; off >>= 1)
        ss += __shfl_xor_sync(FULL, ss, off);

    float scale = 2.0f / fmaxf(sqrtf(ss), 1e-12f);
    float2 r;
    r.x = fmaxf(accx * scale, 0.0f);
    r.y = fmaxf(accy * scale, 0.0f);
    reinterpret_cast<float2*>(out + (size_t)node * DIM)[lane] = r;
}

extern "C" void kernel_launch(void* const* d_in, const int* in_sizes, int n_in,
                              void* d_out, int out_size) {
    const float* x = (const float*)d_in[0];
    const int* edge_index = (const int*)d_in[1];
    // d_in[2] = edge_weights: unused by the reference computation.
    float* out = (float*)d_out;

    {
        int total = N_NODES * HPR;  // 3.2M threads (covers N_NODES for cnt-zeroing)
        int threads = 256;
        int blocks = (total + threads - 1) / threads;
        convert_zero_kernel<<<blocks, threads>>>(x);
    }
    {
        int threads = 256;
        int blocks = (N_EDGES + threads - 1) / threads;
        fill_kernel<<<blocks, threads>>>(edge_index);
    }
    {
        long long total = (long long)N_NODES * 32;
        int threads = 256;
        int blocks = (int)((total + threads - 1) / threads);
        pull_kernel<<<blocks, threads>>>(out);
    }
}